// round 9
// baseline (speedup 1.0000x reference)
#include <cuda_runtime.h>
#include <cuda_bf16.h>
#include <cstdint>
#include <cstddef>

#define BSZ 32
#define SEQ 256
#define EMBD 256
#define HIDD 512
#define NTAG 45
#define NTOK (BSZ*SEQ)     // 8192
#define G4H  2048          // 4*HID
#define GN   4096          // both directions
#define RS   572           // lstm smem row stride (floats)

typedef unsigned long long u64v2;   // packed f32x2

__device__ __forceinline__ void fma2_(u64v2& d, u64v2 a, u64v2 b) {
    asm("fma.rn.f32x2 %0, %1, %2, %0;" : "+l"(d) : "l"(a), "l"(b));
}
__device__ __forceinline__ float unpack_sum_(u64v2 v) {
    float lo, hi;
    asm("mov.b64 {%0, %1}, %2;" : "=f"(lo), "=f"(hi) : "l"(v));
    return lo + hi;
}
__device__ __forceinline__ uint32_t smem_u32_(const void* p) {
    uint32_t a;
    asm("{ .reg .u64 t; cvta.to.shared.u64 t, %1; cvt.u32.u64 %0, t; }" : "=r"(a) : "l"(p));
    return a;
}

// ---------------- scratch ----------------
__device__ __align__(16) float g_G[(size_t)NTOK * GN];            // input proj + bias
__device__ __align__(16) float g_hseq[2 * SEQ * BSZ * HIDD];      // [dir][t][b][h]
__device__ __align__(16) float g_em[(size_t)NTOK * NTAG];         // emissions
__device__ __align__(16) unsigned short g_Wbf[(size_t)GN * EMBD]; // bf16 weights
__device__ __align__(16) unsigned short g_Abf[(size_t)NTOK * EMBD]; // bf16 gathered emb
__device__ float g_loss[BSZ];
__device__ unsigned g_cnt4[4 * 32];                               // lstm barrier slots
__device__ unsigned g_gen4[4 * 32];                               // monotonic generations

// =====================================================================
// Kernel 0a: W = concat(w_ih_f, w_ih_b) fp32 -> bf16
// =====================================================================
__global__ __launch_bounds__(256) void conv_w(
    const float* __restrict__ wf, const float* __restrict__ wb)
{
    for (int idx = blockIdx.x * 256 + threadIdx.x; idx < GN * EMBD; idx += gridDim.x * 256) {
        int n = idx >> 8, k = idx & 255;
        float v = (n < G4H) ? wf[(size_t)n * EMBD + k] : wb[(size_t)(n - G4H) * EMBD + k];
        unsigned short b;
        asm("cvt.rn.bf16.f32 %0, %1;" : "=h"(b) : "f"(v));
        g_Wbf[idx] = b;
    }
}

// =====================================================================
// Kernel 0b: A[tok][k] = bf16(emb[x[tok]][k])
// =====================================================================
__global__ __launch_bounds__(256) void conv_a(
    const int* __restrict__ x, const float* __restrict__ emb)
{
    for (int idx = blockIdx.x * 256 + threadIdx.x; idx < NTOK * EMBD; idx += gridDim.x * 256) {
        int tok = idx >> 8, k = idx & 255;
        float v = emb[(size_t)x[tok] * EMBD + k];
        unsigned short b;
        asm("cvt.rn.bf16.f32 %0, %1;" : "=h"(b) : "f"(v));
        g_Abf[idx] = b;
    }
}

// =====================================================================
// Kernel 1: HMMA bf16 GEMM (mma.sync.m16n8k16, TN).
// Block 128x128, 8 warps (2m x 4n), warp tile 64x32, K chunks of 64.
// smem rows = 64 bf16 = 128B, chunk swizzle c ^= (r&7).
// =====================================================================
__global__ __launch_bounds__(256) void gemm_mma(
    const float* __restrict__ bf, const float* __restrict__ bb)
{
    __shared__ __align__(128) unsigned short sA[128 * 64];
    __shared__ __align__(128) unsigned short sB[128 * 64];
    const int tid = threadIdx.x;
    const int wid = tid >> 5;
    const int lane = tid & 31;
    const int warp_m = (wid >> 2) * 64;
    const int warp_n = (wid & 3) * 32;
    const int m0 = blockIdx.y * 128;
    const int n0 = blockIdx.x * 128;

    float acc[4][4][4];
#pragma unroll
    for (int mt = 0; mt < 4; ++mt)
#pragma unroll
        for (int nt = 0; nt < 4; ++nt)
#pragma unroll
            for (int q = 0; q < 4; ++q) acc[mt][nt][q] = 0.f;

    // ldmatrix source addresses (fixed per lane, offset by tile/kstep)
    const int a_row = (lane & 7) + ((lane >> 3) & 1) * 8;   // + mt*16 + warp_m
    const int a_kh  = (lane >> 4) & 1;                      // k-half selector
    const int b_row = (lane & 7) + ((lane >> 4) & 1) * 8;   // + np*16 + warp_n
    const int b_kh  = (lane >> 3) & 1;

    for (int kb = 0; kb < EMBD; kb += 64) {
        // ---- load tiles: 128 rows x 8 chunks(16B); 4 chunks/thread ----
        for (int i = tid; i < 1024; i += 256) {
            int r = i >> 3, c = i & 7;
            uint4 va = *(const uint4*)&g_Abf[(size_t)(m0 + r) * EMBD + kb + c * 8];
            *(uint4*)&sA[r * 64 + ((c ^ (r & 7)) << 3)] = va;
            uint4 vb = *(const uint4*)&g_Wbf[(size_t)(n0 + r) * EMBD + kb + c * 8];
            *(uint4*)&sB[r * 64 + ((c ^ (r & 7)) << 3)] = vb;
        }
        __syncthreads();
#pragma unroll
        for (int ks = 0; ks < 4; ++ks) {
            uint32_t afr[4][4];
#pragma unroll
            for (int mt = 0; mt < 4; ++mt) {
                int row = warp_m + mt * 16 + a_row;
                int chunk = ks * 2 + a_kh;
                uint32_t addr = smem_u32_(&sA[row * 64 + ((chunk ^ (row & 7)) << 3)]);
                asm volatile("ldmatrix.sync.aligned.m8n8.x4.shared.b16 {%0,%1,%2,%3}, [%4];"
                             : "=r"(afr[mt][0]), "=r"(afr[mt][1]), "=r"(afr[mt][2]), "=r"(afr[mt][3])
                             : "r"(addr));
            }
            uint32_t bfr[2][4];
#pragma unroll
            for (int np = 0; np < 2; ++np) {
                int row = warp_n + np * 16 + b_row;
                int chunk = ks * 2 + b_kh;
                uint32_t addr = smem_u32_(&sB[row * 64 + ((chunk ^ (row & 7)) << 3)]);
                asm volatile("ldmatrix.sync.aligned.m8n8.x4.shared.b16 {%0,%1,%2,%3}, [%4];"
                             : "=r"(bfr[np][0]), "=r"(bfr[np][1]), "=r"(bfr[np][2]), "=r"(bfr[np][3])
                             : "r"(addr));
            }
#pragma unroll
            for (int mt = 0; mt < 4; ++mt)
#pragma unroll
                for (int nt = 0; nt < 4; ++nt) {
                    const uint32_t* bp = &bfr[nt >> 1][(nt & 1) * 2];
                    asm volatile(
                        "mma.sync.aligned.m16n8k16.row.col.f32.bf16.bf16.f32 "
                        "{%0,%1,%2,%3}, {%4,%5,%6,%7}, {%8,%9}, {%0,%1,%2,%3};"
                        : "+f"(acc[mt][nt][0]), "+f"(acc[mt][nt][1]),
                          "+f"(acc[mt][nt][2]), "+f"(acc[mt][nt][3])
                        : "r"(afr[mt][0]), "r"(afr[mt][1]), "r"(afr[mt][2]), "r"(afr[mt][3]),
                          "r"(bp[0]), "r"(bp[1]));
                }
        }
        __syncthreads();
    }

    // ---- epilogue: D[q][2p..], add bias ----
    const int q = lane >> 2, p = lane & 3;
#pragma unroll
    for (int nt = 0; nt < 4; ++nt) {
        int n = n0 + warp_n + nt * 8 + p * 2;
        float b0 = (n < G4H) ? bf[n] : bb[n - G4H];
        float b1 = (n + 1 < G4H) ? bf[n + 1] : bb[n + 1 - G4H];
#pragma unroll
        for (int mt = 0; mt < 4; ++mt) {
            int m = m0 + warp_m + mt * 16 + q;
            float2 v0 = make_float2(acc[mt][nt][0] + b0, acc[mt][nt][1] + b1);
            float2 v1 = make_float2(acc[mt][nt][2] + b0, acc[mt][nt][3] + b1);
            *(float2*)&g_G[(size_t)m * GN + n] = v0;
            *(float2*)&g_G[(size_t)(m + 8) * GN + n] = v1;
        }
    }
}

// =====================================================================
// Kernel 2: persistent bidirectional LSTM recurrence (proven R6 version)
// =====================================================================
__device__ __forceinline__ float sigmoidf_(float v) { return 1.f / (1.f + __expf(-v)); }

__global__ __launch_bounds__(256) void lstm_rec(
    const float* __restrict__ whf, const float* __restrict__ whb)
{
    extern __shared__ float smemf[];
    float* sw  = smemf;                 // 32 rows x RS
    float* sh  = smemf + 32 * RS;       // 16 rows x RS
    float* red = smemf + 48 * RS;       // [16 kseg][16 unit] x 36

    const int tid = threadIdx.x;
    const int dir = blockIdx.x >> 6;
    const int blk = blockIdx.x & 63;
    const int jbase = blk * 8;
    const float* whh = dir ? whb : whf;

    for (int idx = tid; idx < 32 * 128; idx += 256) {
        int row = idx >> 7;
        int q4 = idx & 127;
        int g = row >> 3, j = row & 7;
        float4 v = *(const float4*)(whh + (size_t)(g * 512 + jbase + j) * HIDD + q4 * 4);
        *(float4*)&sw[row * RS + q4 * 4 + 4 * (q4 >> 3)] = v;
    }

    const int kseg = tid >> 4;
    const int unit = tid & 15;
    const int jj = unit & 7;
    const int bo = unit >> 3;
    const int kb = kseg * 36;

    const int fj = tid & 7;
    const int fb = tid >> 3;
    const int jglob = jbase + fj;
    const int fgrp = fb >> 4;
    const int fbl = fb & 15;
    const int funit = fj + 8 * (fbl >> 3);
    const int fbb = fbl & 7;

    unsigned gb0 = 0, gb1 = 0;
    if (tid == 0) {
        gb0 = *(volatile unsigned*)&g_gen4[(dir * 2 + 0) * 32];
        gb1 = *(volatile unsigned*)&g_gen4[(dir * 2 + 1) * 32];
    }

    float c_state = 0.f;
    __syncthreads();

    for (int t = 0; t < SEQ; ++t) {
        const int t_eff = dir ? (SEQ - 1 - t) : t;
        const float* Grow = g_G + (size_t)(fb * SEQ + t_eff) * GN + dir * G4H;
        float pg0 = __ldg(Grow + jglob);
        float pg1 = __ldg(Grow + 512 + jglob);
        float pg2 = __ldg(Grow + 1024 + jglob);
        float pg3 = __ldg(Grow + 1536 + jglob);

#pragma unroll
        for (int grp = 0; grp < 2; ++grp) {
            const int slot = (dir * 2 + grp) * 32;
            float d0 = 0.f, d1 = 0.f, d2 = 0.f, d3 = 0.f;
            if (t > 0) {
                if (tid == 0) {
                    unsigned base = grp ? gb1 : gb0;
                    while ((unsigned)(*(volatile unsigned*)&g_gen4[slot] - base) < (unsigned)t) { }
                    __threadfence();
                }
                __syncthreads();
                const int prev_te = dir ? (t_eff + 1) : (t_eff - 1);
                const float* hsrc = g_hseq + (size_t)((dir * SEQ + prev_te) * BSZ + grp * 16) * HIDD;
                for (int idx = tid; idx < 16 * 128; idx += 256) {
                    int b = idx >> 7;
                    int q4 = idx & 127;
                    float4 v = __ldcg((const float4*)(hsrc + b * HIDD + q4 * 4));
                    *(float4*)&sh[b * RS + q4 * 4 + 4 * (q4 >> 3)] = v;
                }
                __syncthreads();
                u64v2 acc2[4][8];
#pragma unroll
                for (int g = 0; g < 4; ++g)
#pragma unroll
                    for (int bb = 0; bb < 8; ++bb) acc2[g][bb] = 0ull;
                const float* w0p = &sw[jj * RS + kb];
                const float* w1p = w0p + 8 * RS;
                const float* w2p = w0p + 16 * RS;
                const float* w3p = w0p + 24 * RS;
                const float* hp  = &sh[(bo * 8) * RS + kb];
#pragma unroll
                for (int kk = 0; kk < 32; kk += 4) {
                    ulonglong2 w0 = *(const ulonglong2*)(w0p + kk);
                    ulonglong2 w1 = *(const ulonglong2*)(w1p + kk);
                    ulonglong2 w2 = *(const ulonglong2*)(w2p + kk);
                    ulonglong2 w3 = *(const ulonglong2*)(w3p + kk);
#pragma unroll
                    for (int bb = 0; bb < 8; ++bb) {
                        ulonglong2 h = *(const ulonglong2*)(hp + bb * RS + kk);
                        fma2_(acc2[0][bb], w0.x, h.x); fma2_(acc2[0][bb], w0.y, h.y);
                        fma2_(acc2[1][bb], w1.x, h.x); fma2_(acc2[1][bb], w1.y, h.y);
                        fma2_(acc2[2][bb], w2.x, h.x); fma2_(acc2[2][bb], w2.y, h.y);
                        fma2_(acc2[3][bb], w3.x, h.x); fma2_(acc2[3][bb], w3.y, h.y);
                    }
                }
                float* rp = &red[(kseg * 16 + unit) * 36];
#pragma unroll
                for (int g = 0; g < 4; ++g) {
                    float s0 = unpack_sum_(acc2[g][0]);
                    float s1 = unpack_sum_(acc2[g][1]);
                    float s2 = unpack_sum_(acc2[g][2]);
                    float s3 = unpack_sum_(acc2[g][3]);
                    float s4 = unpack_sum_(acc2[g][4]);
                    float s5 = unpack_sum_(acc2[g][5]);
                    float s6 = unpack_sum_(acc2[g][6]);
                    float s7 = unpack_sum_(acc2[g][7]);
                    *(float4*)&rp[g * 8]     = make_float4(s0, s1, s2, s3);
                    *(float4*)&rp[g * 8 + 4] = make_float4(s4, s5, s6, s7);
                }
                __syncthreads();
                if (fgrp == grp) {
#pragma unroll
                    for (int s = 0; s < 16; ++s) {
                        const float* rr = &red[(s * 16 + funit) * 36];
                        d0 += rr[fbb];
                        d1 += rr[8 + fbb];
                        d2 += rr[16 + fbb];
                        d3 += rr[24 + fbb];
                    }
                }
            }
            if (fgrp == grp) {
                float gi = pg0 + d0;
                float gf = pg1 + d1;
                float gg = pg2 + d2;
                float go = pg3 + d3;
                float iv = sigmoidf_(gi);
                float fv = sigmoidf_(gf);
                float ov = sigmoidf_(go);
                float gv = tanhf(gg);
                c_state = fv * c_state + iv * gv;
                float hv = ov * tanhf(c_state);
                __stcg(&g_hseq[(size_t)((dir * SEQ + t_eff) * BSZ + fb) * HIDD + jglob], hv);
            }
            __threadfence();
            __syncthreads();
            if (tid == 0) {
                if (atomicAdd(&g_cnt4[slot], 1u) == 63u) {
                    g_cnt4[slot] = 0u;
                    __threadfence();
                    *(volatile unsigned*)&g_gen4[slot] =
                        *(volatile unsigned*)&g_gen4[slot] + 1u;
                }
            }
        }
    }
}

// =====================================================================
// Kernel 3: emissions
// =====================================================================
__device__ __forceinline__ float dot4_(float4 a, float4 b) {
    return a.x * b.x + a.y * b.y + a.z * b.z + a.w * b.w;
}

__global__ __launch_bounds__(256) void emis_k(
    const float* __restrict__ lw, const float* __restrict__ lb)
{
    __shared__ float shh[32 * 132];
    __shared__ float shw[48 * 132];
    const int tid = threadIdx.x;
    const int blk = blockIdx.x;
    const int b = blk >> 3;
    const int s0 = (blk & 7) * 32;
    const int tt = tid & 15;
    const int tg = tid >> 4;
    float acc[2][3] = {{0.f, 0.f, 0.f}, {0.f, 0.f, 0.f}};

    for (int kc = 0; kc < 1024; kc += 128) {
        __syncthreads();
        const int dk = kc >> 9;
        const int ko = kc & 511;
        for (int idx = tid; idx < 32 * 32; idx += 256) {
            int ti = idx >> 5;
            int q = (idx & 31) * 4;
            *(float4*)&shh[ti * 132 + q] =
                *(const float4*)&g_hseq[(size_t)((dk * SEQ + (s0 + ti)) * BSZ + b) * HIDD + ko + q];
        }
        for (int idx = tid; idx < 48 * 32; idx += 256) {
            int tag = idx >> 5;
            int q = (idx & 31) * 4;
            float4 v = make_float4(0.f, 0.f, 0.f, 0.f);
            if (tag < NTAG) v = *(const float4*)&lw[(size_t)tag * 1024 + kc + q];
            *(float4*)&shw[tag * 132 + q] = v;
        }
        __syncthreads();
#pragma unroll 8
        for (int kk = 0; kk < 128; kk += 4) {
            float4 h0 = *(const float4*)&shh[tt * 132 + kk];
            float4 h1 = *(const float4*)&shh[(tt + 16) * 132 + kk];
            float4 w0 = *(const float4*)&shw[tg * 132 + kk];
            float4 w1 = *(const float4*)&shw[(tg + 16) * 132 + kk];
            float4 w2 = *(const float4*)&shw[(tg + 32) * 132 + kk];
            acc[0][0] += dot4_(h0, w0); acc[0][1] += dot4_(h0, w1); acc[0][2] += dot4_(h0, w2);
            acc[1][0] += dot4_(h1, w0); acc[1][1] += dot4_(h1, w1); acc[1][2] += dot4_(h1, w2);
        }
    }
#pragma unroll
    for (int ti = 0; ti < 2; ++ti) {
        int token = b * SEQ + s0 + tt + ti * 16;
#pragma unroll
        for (int c = 0; c < 3; ++c) {
            int tag = tg + c * 16;
            if (tag < NTAG)
                g_em[(size_t)token * NTAG + tag] = acc[ti][c] + lb[tag];
        }
    }
}

// =====================================================================
// Kernel 4: CRF — one WARP per batch, warp-synchronous exp-domain
// forward with lazy renorm (every 8 steps). 4 warps/block, grid 8.
// =====================================================================
__global__ __launch_bounds__(128) void crf_k(
    const int* __restrict__ tags, const float* __restrict__ st,
    const float* __restrict__ et, const float* __restrict__ tr)
{
    __shared__ float str[NTAG * NTAG];
    __shared__ float sE[NTAG * 48];
    __shared__ float sa[4][2][48];
    const int tid = threadIdx.x;
    const int wid = tid >> 5;
    const int lane = tid & 31;
    const int b = blockIdx.x * 4 + wid;
    const int* tg = tags + b * SEQ;

    for (int i = tid; i < NTAG * NTAG; i += 128) str[i] = tr[i];
    __syncthreads();
    for (int idx = tid; idx < NTAG * NTAG; idx += 128) {
        int i = idx / NTAG, col = idx % NTAG;
        sE[i * 48 + col] = __expf(str[idx]);
    }
    __syncthreads();

    // ---- gold path score (warp-reduced, fixed shuffle order) ----
    float part = 0.f;
    for (int s = lane; s < SEQ; s += 32) {
        int cur = tg[s];
        part += g_em[(size_t)(b * SEQ + s) * NTAG + cur];
        if (s + 1 < SEQ) part += str[cur * NTAG + tg[s + 1]];
    }
#pragma unroll
    for (int off = 16; off; off >>= 1)
        part += __shfl_xor_sync(0xffffffffu, part, off);

    // ---- forward algorithm ----
    const int c0 = lane;                       // always < 45
    const bool has1 = (lane < 13);
    const int c1 = has1 ? lane + 32 : lane;
    float* a0 = sa[wid][0];
    float* a1 = sa[wid][1];

    float i0 = st[c0] + g_em[(size_t)(b * SEQ) * NTAG + c0];
    float i1 = has1 ? (st[c1] + g_em[(size_t)(b * SEQ) * NTAG + c1]) : -1e30f;
    float m = fmaxf(i0, i1);
#pragma unroll
    for (int off = 16; off; off >>= 1)
        m = fmaxf(m, __shfl_xor_sync(0xffffffffu, m, off));
    float logacc = m;
    a0[c0] = __expf(i0 - m);
    if (has1) a0[c1] = __expf(i1 - m);
    __syncwarp();

    float e0 = g_em[(size_t)(b * SEQ + 1) * NTAG + c0];
    float e1 = has1 ? g_em[(size_t)(b * SEQ + 1) * NTAG + c1] : 0.f;
    int cur = 0;
    for (int t = 1; t < SEQ; ++t) {
        float n0 = 0.f, n1 = 0.f;
        if (t + 1 < SEQ) {
            n0 = g_em[(size_t)(b * SEQ + t + 1) * NTAG + c0];
            if (has1) n1 = g_em[(size_t)(b * SEQ + t + 1) * NTAG + c1];
        }
        const float* a = cur ? a1 : a0;
        float* an = cur ? a0 : a1;
        float s0 = 0.f, s1 = 0.f;
#pragma unroll 9
        for (int i = 0; i < NTAG; ++i) {
            float ai = a[i];
            s0 += sE[i * 48 + c0] * ai;
            s1 += sE[i * 48 + c1] * ai;
        }
        float v0 = s0 * __expf(e0);
        an[c0] = v0;
        float v1 = 0.f;
        if (has1) { v1 = s1 * __expf(e1); an[c1] = v1; }
        __syncwarp();
        cur ^= 1;
        if ((t & 7) == 0) {
            float mm = fmaxf(v0, v1);
#pragma unroll
            for (int off = 16; off; off >>= 1)
                mm = fmaxf(mm, __shfl_xor_sync(0xffffffffu, mm, off));
            float inv = 1.f / mm;
            float* ac = cur ? a1 : a0;
            ac[c0] *= inv;
            if (has1) ac[c1] *= inv;
            logacc += __logf(mm);
            __syncwarp();
        }
        e0 = n0; e1 = n1;
    }

    const float* af = cur ? a1 : a0;
    float ssum = af[c0] * __expf(et[c0]);
    if (has1) ssum += af[c1] * __expf(et[c1]);
#pragma unroll
    for (int off = 16; off; off >>= 1)
        ssum += __shfl_xor_sync(0xffffffffu, ssum, off);

    if (lane == 0) {
        float sc = part + st[tg[0]] + et[tg[SEQ - 1]];
        float logZ = logacc + __logf(ssum);
        g_loss[b] = logZ - sc;
    }
}

__global__ void final_reduce(float* __restrict__ out)
{
    if (threadIdx.x == 0) {
        float s = 0.f;
        for (int i = 0; i < BSZ; ++i) s += g_loss[i];
        out[0] = s / (float)BSZ;
    }
}

// =====================================================================
extern "C" void kernel_launch(void* const* d_in, const int* in_sizes, int n_in,
                              void* d_out, int out_size)
{
    (void)in_sizes; (void)n_in; (void)out_size;
    const int*   x   = (const int*)d_in[0];
    const int*   tgs = (const int*)d_in[1];
    const float* emb = (const float*)d_in[2];
    const float* wif = (const float*)d_in[3];
    const float* whf = (const float*)d_in[4];
    const float* bf  = (const float*)d_in[5];
    const float* wib = (const float*)d_in[6];
    const float* whb = (const float*)d_in[7];
    const float* bb  = (const float*)d_in[8];
    const float* lw  = (const float*)d_in[9];
    const float* lb  = (const float*)d_in[10];
    const float* st  = (const float*)d_in[11];
    const float* et  = (const float*)d_in[12];
    const float* tr  = (const float*)d_in[13];
    float* out = (float*)d_out;

    const int rec_smem = (48 * RS + 256 * 36) * 4;   // 146688 B
    cudaFuncSetAttribute(lstm_rec, cudaFuncAttributeMaxDynamicSharedMemorySize, rec_smem);

    conv_w<<<512, 256>>>(wif, wib);
    conv_a<<<512, 256>>>(x, emb);
    dim3 mma_grid(32, 64);
    gemm_mma<<<mma_grid, 256>>>(bf, bb);
    lstm_rec<<<128, 256, rec_smem>>>(whf, whb);
    emis_k<<<256, 256>>>(lw, lb);
    crf_k<<<8, 128>>>(tgs, st, et, tr);
    final_reduce<<<1, 32>>>(out);
}

// round 10
// speedup vs baseline: 1.2698x; 1.2698x over previous
#include <cuda_runtime.h>
#include <cstdint>
#include <cstddef>

#define BSZ 32
#define SEQ 256
#define EMBD 256
#define HIDD 512
#define NTAG 45
#define NTOK (BSZ*SEQ)     // 8192
#define G4H  2048          // 4*HID
#define GN   4096          // both directions
#define RS   572           // lstm smem row stride (floats)

typedef unsigned long long u64v2;   // packed f32x2

__device__ __forceinline__ void fma2_(u64v2& d, u64v2 a, u64v2 b) {
    asm("fma.rn.f32x2 %0, %1, %2, %0;" : "+l"(d) : "l"(a), "l"(b));
}
__device__ __forceinline__ float unpack_sum_(u64v2 v) {
    float lo, hi;
    asm("mov.b64 {%0, %1}, %2;" : "=f"(lo), "=f"(hi) : "l"(v));
    return lo + hi;
}
__device__ __forceinline__ u64v2 pack2_(float lo, float hi) {
    u64v2 r;
    asm("mov.b64 %0, {%1, %2};" : "=l"(r) : "f"(lo), "f"(hi));
    return r;
}

// ---------------- scratch ----------------
__device__ __align__(16) float g_G[(size_t)NTOK * GN];           // input proj + bias
__device__ __align__(16) float g_hseq[2 * SEQ * BSZ * HIDD];     // [dir][t][b][h]
__device__ __align__(16) float g_em[(size_t)NTOK * NTAG];        // emissions
__device__ float g_loss[BSZ];
// two-level barrier: leaf counters (4 slots x 8 subgroups, 256B apart),
// root counters + generation words (proven R3 pattern)
__device__ unsigned g_cnt1[4 * 8 * 64];
__device__ unsigned g_cnt4[4 * 32];
__device__ unsigned g_gen4[4 * 32];

// =====================================================================
// Kernel 1: G[token][n] = dot(emb[x[token]], W[n]) + bias[n]  (f32x2)
// =====================================================================
__global__ __launch_bounds__(256) void gemm_in(
    const int* __restrict__ x, const float* __restrict__ emb,
    const float* __restrict__ wf, const float* __restrict__ wb,
    const float* __restrict__ bf, const float* __restrict__ bb)
{
    __shared__ float sA[16 * 132];
    __shared__ float sW[16 * 132];
    const int tid = threadIdx.x;
    const int bx = blockIdx.x;
    const int by = blockIdx.y;
    const int tx = tid & 15, ty = tid >> 4;

    u64v2 acc2[8][4];
#pragma unroll
    for (int i = 0; i < 8; ++i)
#pragma unroll
        for (int j = 0; j < 4; ++j) acc2[i][j] = 0ull;

    const int f4a = tid * 2, f4b = tid * 2 + 1;
    const int ra = f4a >> 2, qa = (f4a & 3) * 4;
    const int rb = f4b >> 2, qb = (f4b & 3) * 4;
    const float* arow_a = emb + (size_t)x[by * 128 + ra] * EMBD;
    const float* arow_b = emb + (size_t)x[by * 128 + rb] * EMBD;
    const int na = bx * 128 + ra, nb = bx * 128 + rb;
    const float* wrow_a = (na < G4H) ? (wf + (size_t)na * EMBD) : (wb + (size_t)(na - G4H) * EMBD);
    const float* wrow_b = (nb < G4H) ? (wf + (size_t)nb * EMBD) : (wb + (size_t)(nb - G4H) * EMBD);

    for (int kb = 0; kb < EMBD; kb += 16) {
        __syncthreads();
        float4 va = *(const float4*)(arow_a + kb + qa);
        float4 vb = *(const float4*)(arow_b + kb + qb);
        float4 wa = *(const float4*)(wrow_a + kb + qa);
        float4 wv = *(const float4*)(wrow_b + kb + qb);
        sA[(qa + 0) * 132 + ra] = va.x; sA[(qa + 1) * 132 + ra] = va.y;
        sA[(qa + 2) * 132 + ra] = va.z; sA[(qa + 3) * 132 + ra] = va.w;
        sA[(qb + 0) * 132 + rb] = vb.x; sA[(qb + 1) * 132 + rb] = vb.y;
        sA[(qb + 2) * 132 + rb] = vb.z; sA[(qb + 3) * 132 + rb] = vb.w;
        sW[(qa + 0) * 132 + ra] = wa.x; sW[(qa + 1) * 132 + ra] = wa.y;
        sW[(qa + 2) * 132 + ra] = wa.z; sW[(qa + 3) * 132 + ra] = wa.w;
        sW[(qb + 0) * 132 + rb] = wv.x; sW[(qb + 1) * 132 + rb] = wv.y;
        sW[(qb + 2) * 132 + rb] = wv.z; sW[(qb + 3) * 132 + rb] = wv.w;
        __syncthreads();
#pragma unroll
        for (int kk = 0; kk < 16; ++kk) {
            float4 a0 = *(const float4*)&sA[kk * 132 + ty * 8];
            float4 a1 = *(const float4*)&sA[kk * 132 + ty * 8 + 4];
            ulonglong2 b0 = *(const ulonglong2*)&sW[kk * 132 + tx * 8];
            ulonglong2 b1 = *(const ulonglong2*)&sW[kk * 132 + tx * 8 + 4];
            float av[8] = {a0.x, a0.y, a0.z, a0.w, a1.x, a1.y, a1.z, a1.w};
#pragma unroll
            for (int i = 0; i < 8; ++i) {
                u64v2 aa = pack2_(av[i], av[i]);
                fma2_(acc2[i][0], aa, b0.x);
                fma2_(acc2[i][1], aa, b0.y);
                fma2_(acc2[i][2], aa, b1.x);
                fma2_(acc2[i][3], aa, b1.y);
            }
        }
    }
    const int m0 = by * 128 + ty * 8;
    const int n0 = bx * 128 + tx * 8;
#pragma unroll
    for (int i = 0; i < 8; ++i) {
        float* dst = g_G + (size_t)(m0 + i) * GN + n0;
#pragma unroll
        for (int p = 0; p < 4; ++p) {
            float lo, hi;
            asm("mov.b64 {%0, %1}, %2;" : "=f"(lo), "=f"(hi) : "l"(acc2[i][p]));
            int n_lo = n0 + 2 * p, n_hi = n_lo + 1;
            float bias_lo = (n_lo < G4H) ? bf[n_lo] : bb[n_lo - G4H];
            float bias_hi = (n_hi < G4H) ? bf[n_hi] : bb[n_hi - G4H];
            dst[2 * p]     = lo + bias_lo;
            dst[2 * p + 1] = hi + bias_hi;
        }
    }
}

// =====================================================================
// Kernel 2: persistent bidirectional LSTM recurrence.
// Proven R3/R6 consumer (volatile gen poll); arrival now a two-level
// atomic tree (8x8) to kill the 64-deep single-address atomic chain.
// =====================================================================
__device__ __forceinline__ float sigmoidf_(float v) { return 1.f / (1.f + __expf(-v)); }

__global__ __launch_bounds__(256) void lstm_rec(
    const float* __restrict__ whf, const float* __restrict__ whb)
{
    extern __shared__ float smemf[];
    float* sw  = smemf;                 // 32 rows x RS
    float* sh  = smemf + 32 * RS;       // 16 rows x RS
    float* red = smemf + 48 * RS;       // [16 kseg][16 unit] x 36

    const int tid = threadIdx.x;
    const int dir = blockIdx.x >> 6;
    const int blk = blockIdx.x & 63;
    const int jbase = blk * 8;
    const int sub = blk >> 3;           // 0..7 subgroup for arrival tree
    const float* whh = dir ? whb : whf;

    for (int idx = tid; idx < 32 * 128; idx += 256) {
        int row = idx >> 7;
        int q4 = idx & 127;
        int g = row >> 3, j = row & 7;
        float4 v = *(const float4*)(whh + (size_t)(g * 512 + jbase + j) * HIDD + q4 * 4);
        *(float4*)&sw[row * RS + q4 * 4 + 4 * (q4 >> 3)] = v;
    }

    const int kseg = tid >> 4;
    const int unit = tid & 15;
    const int jj = unit & 7;
    const int bo = unit >> 3;
    const int kb = kseg * 36;

    const int fj = tid & 7;
    const int fb = tid >> 3;
    const int jglob = jbase + fj;
    const int fgrp = fb >> 4;
    const int fbl = fb & 15;
    const int funit = fj + 8 * (fbl >> 3);
    const int fbb = fbl & 7;

    unsigned gb0 = 0, gb1 = 0;
    if (tid == 0) {
        gb0 = *(volatile unsigned*)&g_gen4[(dir * 2 + 0) * 32];
        gb1 = *(volatile unsigned*)&g_gen4[(dir * 2 + 1) * 32];
    }

    float c_state = 0.f;
    __syncthreads();

    for (int t = 0; t < SEQ; ++t) {
        const int t_eff = dir ? (SEQ - 1 - t) : t;
        const float* Grow = g_G + (size_t)(fb * SEQ + t_eff) * GN + dir * G4H;
        float pg0 = __ldg(Grow + jglob);
        float pg1 = __ldg(Grow + 512 + jglob);
        float pg2 = __ldg(Grow + 1024 + jglob);
        float pg3 = __ldg(Grow + 1536 + jglob);

#pragma unroll
        for (int grp = 0; grp < 2; ++grp) {
            const int sl = dir * 2 + grp;        // 0..3
            const int slot = sl * 32;
            float d0 = 0.f, d1 = 0.f, d2 = 0.f, d3 = 0.f;
            if (t > 0) {
                if (tid == 0) {
                    unsigned base = grp ? gb1 : gb0;
                    while ((unsigned)(*(volatile unsigned*)&g_gen4[slot] - base) < (unsigned)t) { }
                    __threadfence();
                }
                __syncthreads();
                const int prev_te = dir ? (t_eff + 1) : (t_eff - 1);
                const float* hsrc = g_hseq + (size_t)((dir * SEQ + prev_te) * BSZ + grp * 16) * HIDD;
                for (int idx = tid; idx < 16 * 128; idx += 256) {
                    int b = idx >> 7;
                    int q4 = idx & 127;
                    float4 v = __ldcg((const float4*)(hsrc + b * HIDD + q4 * 4));
                    *(float4*)&sh[b * RS + q4 * 4 + 4 * (q4 >> 3)] = v;
                }
                __syncthreads();
                u64v2 acc2[4][8];
#pragma unroll
                for (int g = 0; g < 4; ++g)
#pragma unroll
                    for (int bb = 0; bb < 8; ++bb) acc2[g][bb] = 0ull;
                const float* w0p = &sw[jj * RS + kb];
                const float* w1p = w0p + 8 * RS;
                const float* w2p = w0p + 16 * RS;
                const float* w3p = w0p + 24 * RS;
                const float* hp  = &sh[(bo * 8) * RS + kb];
#pragma unroll
                for (int kk = 0; kk < 32; kk += 4) {
                    ulonglong2 w0 = *(const ulonglong2*)(w0p + kk);
                    ulonglong2 w1 = *(const ulonglong2*)(w1p + kk);
                    ulonglong2 w2 = *(const ulonglong2*)(w2p + kk);
                    ulonglong2 w3 = *(const ulonglong2*)(w3p + kk);
#pragma unroll
                    for (int bb = 0; bb < 8; ++bb) {
                        ulonglong2 h = *(const ulonglong2*)(hp + bb * RS + kk);
                        fma2_(acc2[0][bb], w0.x, h.x); fma2_(acc2[0][bb], w0.y, h.y);
                        fma2_(acc2[1][bb], w1.x, h.x); fma2_(acc2[1][bb], w1.y, h.y);
                        fma2_(acc2[2][bb], w2.x, h.x); fma2_(acc2[2][bb], w2.y, h.y);
                        fma2_(acc2[3][bb], w3.x, h.x); fma2_(acc2[3][bb], w3.y, h.y);
                    }
                }
                float* rp = &red[(kseg * 16 + unit) * 36];
#pragma unroll
                for (int g = 0; g < 4; ++g) {
                    float s0 = unpack_sum_(acc2[g][0]);
                    float s1 = unpack_sum_(acc2[g][1]);
                    float s2 = unpack_sum_(acc2[g][2]);
                    float s3 = unpack_sum_(acc2[g][3]);
                    float s4 = unpack_sum_(acc2[g][4]);
                    float s5 = unpack_sum_(acc2[g][5]);
                    float s6 = unpack_sum_(acc2[g][6]);
                    float s7 = unpack_sum_(acc2[g][7]);
                    *(float4*)&rp[g * 8]     = make_float4(s0, s1, s2, s3);
                    *(float4*)&rp[g * 8 + 4] = make_float4(s4, s5, s6, s7);
                }
                __syncthreads();
                if (fgrp == grp) {
#pragma unroll
                    for (int s = 0; s < 16; ++s) {
                        const float* rr = &red[(s * 16 + funit) * 36];
                        d0 += rr[fbb];
                        d1 += rr[8 + fbb];
                        d2 += rr[16 + fbb];
                        d3 += rr[24 + fbb];
                    }
                }
            }
            if (fgrp == grp) {
                float gi = pg0 + d0;
                float gf = pg1 + d1;
                float gg = pg2 + d2;
                float go = pg3 + d3;
                float iv = sigmoidf_(gi);
                float fv = sigmoidf_(gf);
                float ov = sigmoidf_(go);
                float gv = tanhf(gg);
                c_state = fv * c_state + iv * gv;
                float hv = ov * tanhf(c_state);
                __stcg(&g_hseq[(size_t)((dir * SEQ + t_eff) * BSZ + fb) * HIDD + jglob], hv);
            }
            __threadfence();
            __syncthreads();
            if (tid == 0) {
                // two-level arrival: 8 leaf counters (256B apart) -> root -> gen
                unsigned* leaf = &g_cnt1[(sl * 8 + sub) * 64];
                if (atomicAdd(leaf, 1u) == 7u) {
                    atomicExch(leaf, 0u);               // coherent reset (same-address order)
                    if (atomicAdd(&g_cnt4[slot], 1u) == 7u) {
                        g_cnt4[slot] = 0u;
                        __threadfence();
                        *(volatile unsigned*)&g_gen4[slot] =
                            *(volatile unsigned*)&g_gen4[slot] + 1u;
                    }
                }
            }
        }
    }
}

// =====================================================================
// Kernel 3: emissions
// =====================================================================
__device__ __forceinline__ float dot4_(float4 a, float4 b) {
    return a.x * b.x + a.y * b.y + a.z * b.z + a.w * b.w;
}

__global__ __launch_bounds__(256) void emis_k(
    const float* __restrict__ lw, const float* __restrict__ lb)
{
    __shared__ float shh[32 * 132];
    __shared__ float shw[48 * 132];
    const int tid = threadIdx.x;
    const int blk = blockIdx.x;
    const int b = blk >> 3;
    const int s0 = (blk & 7) * 32;
    const int tt = tid & 15;
    const int tg = tid >> 4;
    float acc[2][3] = {{0.f, 0.f, 0.f}, {0.f, 0.f, 0.f}};

    for (int kc = 0; kc < 1024; kc += 128) {
        __syncthreads();
        const int dk = kc >> 9;
        const int ko = kc & 511;
        for (int idx = tid; idx < 32 * 32; idx += 256) {
            int ti = idx >> 5;
            int q = (idx & 31) * 4;
            *(float4*)&shh[ti * 132 + q] =
                *(const float4*)&g_hseq[(size_t)((dk * SEQ + (s0 + ti)) * BSZ + b) * HIDD + ko + q];
        }
        for (int idx = tid; idx < 48 * 32; idx += 256) {
            int tag = idx >> 5;
            int q = (idx & 31) * 4;
            float4 v = make_float4(0.f, 0.f, 0.f, 0.f);
            if (tag < NTAG) v = *(const float4*)&lw[(size_t)tag * 1024 + kc + q];
            *(float4*)&shw[tag * 132 + q] = v;
        }
        __syncthreads();
#pragma unroll 8
        for (int kk = 0; kk < 128; kk += 4) {
            float4 h0 = *(const float4*)&shh[tt * 132 + kk];
            float4 h1 = *(const float4*)&shh[(tt + 16) * 132 + kk];
            float4 w0 = *(const float4*)&shw[tg * 132 + kk];
            float4 w1 = *(const float4*)&shw[(tg + 16) * 132 + kk];
            float4 w2 = *(const float4*)&shw[(tg + 32) * 132 + kk];
            acc[0][0] += dot4_(h0, w0); acc[0][1] += dot4_(h0, w1); acc[0][2] += dot4_(h0, w2);
            acc[1][0] += dot4_(h1, w0); acc[1][1] += dot4_(h1, w1); acc[1][2] += dot4_(h1, w2);
        }
    }
#pragma unroll
    for (int ti = 0; ti < 2; ++ti) {
        int token = b * SEQ + s0 + tt + ti * 16;
#pragma unroll
        for (int c = 0; c < 3; ++c) {
            int tag = tg + c * 16;
            if (tag < NTAG)
                g_em[(size_t)token * NTAG + tag] = acc[ti][c] + lb[tag];
        }
    }
}

// =====================================================================
// Kernel 4: CRF — one WARP per batch (proven R9), exp-domain forward
// with lazy renorm (every 8 steps). 4 warps/block, grid 8.
// =====================================================================
__global__ __launch_bounds__(128) void crf_k(
    const int* __restrict__ tags, const float* __restrict__ st,
    const float* __restrict__ et, const float* __restrict__ tr)
{
    __shared__ float str[NTAG * NTAG];
    __shared__ float sE[NTAG * 48];
    __shared__ float sa[4][2][48];
    const int tid = threadIdx.x;
    const int wid = tid >> 5;
    const int lane = tid & 31;
    const int b = blockIdx.x * 4 + wid;
    const int* tg = tags + b * SEQ;

    for (int i = tid; i < NTAG * NTAG; i += 128) str[i] = tr[i];
    __syncthreads();
    for (int idx = tid; idx < NTAG * NTAG; idx += 128) {
        int i = idx / NTAG, col = idx % NTAG;
        sE[i * 48 + col] = __expf(str[idx]);
    }
    __syncthreads();

    float part = 0.f;
    for (int s = lane; s < SEQ; s += 32) {
        int cur = tg[s];
        part += g_em[(size_t)(b * SEQ + s) * NTAG + cur];
        if (s + 1 < SEQ) part += str[cur * NTAG + tg[s + 1]];
    }
#pragma unroll
    for (int off = 16; off; off >>= 1)
        part += __shfl_xor_sync(0xffffffffu, part, off);

    const int c0 = lane;
    const bool has1 = (lane < 13);
    const int c1 = has1 ? lane + 32 : lane;
    float* a0 = sa[wid][0];
    float* a1 = sa[wid][1];

    float i0 = st[c0] + g_em[(size_t)(b * SEQ) * NTAG + c0];
    float i1 = has1 ? (st[c1] + g_em[(size_t)(b * SEQ) * NTAG + c1]) : -1e30f;
    float m = fmaxf(i0, i1);
#pragma unroll
    for (int off = 16; off; off >>= 1)
        m = fmaxf(m, __shfl_xor_sync(0xffffffffu, m, off));
    float logacc = m;
    a0[c0] = __expf(i0 - m);
    if (has1) a0[c1] = __expf(i1 - m);
    __syncwarp();

    float e0 = g_em[(size_t)(b * SEQ + 1) * NTAG + c0];
    float e1 = has1 ? g_em[(size_t)(b * SEQ + 1) * NTAG + c1] : 0.f;
    int cur = 0;
    for (int t = 1; t < SEQ; ++t) {
        float n0 = 0.f, n1 = 0.f;
        if (t + 1 < SEQ) {
            n0 = g_em[(size_t)(b * SEQ + t + 1) * NTAG + c0];
            if (has1) n1 = g_em[(size_t)(b * SEQ + t + 1) * NTAG + c1];
        }
        const float* a = cur ? a1 : a0;
        float* an = cur ? a0 : a1;
        float s0 = 0.f, s1 = 0.f;
#pragma unroll 9
        for (int i = 0; i < NTAG; ++i) {
            float ai = a[i];
            s0 += sE[i * 48 + c0] * ai;
            s1 += sE[i * 48 + c1] * ai;
        }
        float v0 = s0 * __expf(e0);
        an[c0] = v0;
        float v1 = 0.f;
        if (has1) { v1 = s1 * __expf(e1); an[c1] = v1; }
        __syncwarp();
        cur ^= 1;
        if ((t & 7) == 0) {
            float mm = fmaxf(v0, v1);
#pragma unroll
            for (int off = 16; off; off >>= 1)
                mm = fmaxf(mm, __shfl_xor_sync(0xffffffffu, mm, off));
            float inv = 1.f / mm;
            float* ac = cur ? a1 : a0;
            ac[c0] *= inv;
            if (has1) ac[c1] *= inv;
            logacc += __logf(mm);
            __syncwarp();
        }
        e0 = n0; e1 = n1;
    }

    const float* af = cur ? a1 : a0;
    float ssum = af[c0] * __expf(et[c0]);
    if (has1) ssum += af[c1] * __expf(et[c1]);
#pragma unroll
    for (int off = 16; off; off >>= 1)
        ssum += __shfl_xor_sync(0xffffffffu, ssum, off);

    if (lane == 0) {
        float sc = part + st[tg[0]] + et[tg[SEQ - 1]];
        float logZ = logacc + __logf(ssum);
        g_loss[b] = logZ - sc;
    }
}

__global__ void final_reduce(float* __restrict__ out)
{
    if (threadIdx.x == 0) {
        float s = 0.f;
        for (int i = 0; i < BSZ; ++i) s += g_loss[i];
        out[0] = s / (float)BSZ;
    }
}

// =====================================================================
extern "C" void kernel_launch(void* const* d_in, const int* in_sizes, int n_in,
                              void* d_out, int out_size)
{
    (void)in_sizes; (void)n_in; (void)out_size;
    const int*   x   = (const int*)d_in[0];
    const int*   tgs = (const int*)d_in[1];
    const float* emb = (const float*)d_in[2];
    const float* wif = (const float*)d_in[3];
    const float* whf = (const float*)d_in[4];
    const float* bf  = (const float*)d_in[5];
    const float* wib = (const float*)d_in[6];
    const float* whb = (const float*)d_in[7];
    const float* bb  = (const float*)d_in[8];
    const float* lw  = (const float*)d_in[9];
    const float* lb  = (const float*)d_in[10];
    const float* st  = (const float*)d_in[11];
    const float* et  = (const float*)d_in[12];
    const float* tr  = (const float*)d_in[13];
    float* out = (float*)d_out;

    const int rec_smem = (48 * RS + 256 * 36) * 4;   // 146688 B
    cudaFuncSetAttribute(lstm_rec, cudaFuncAttributeMaxDynamicSharedMemorySize, rec_smem);

    dim3 gemm_grid(32, 64);
    gemm_in<<<gemm_grid, 256>>>(x, emb, wif, wib, bf, bb);
    lstm_rec<<<128, 256, rec_smem>>>(whf, whb);
    emis_k<<<256, 256>>>(lw, lb);
    crf_k<<<8, 128>>>(tgs, st, et, tr);
    final_reduce<<<1, 32>>>(out);
}

// round 12
// speedup vs baseline: 1.8022x; 1.4192x over previous
#include <cuda_runtime.h>
#include <cstdint>
#include <cstddef>

#define BSZ 32
#define SEQ 256
#define EMBD 256
#define HIDD 512
#define NTAG 45
#define NTOK (BSZ*SEQ)     // 8192
#define G4H  2048          // 4*HID
#define GN   4096          // both directions
#define RS   572           // lstm smem row stride (floats)

typedef unsigned long long u64v2;   // packed f32x2

__device__ __forceinline__ void fma2_(u64v2& d, u64v2 a, u64v2 b) {
    asm("fma.rn.f32x2 %0, %1, %2, %0;" : "+l"(d) : "l"(a), "l"(b));
}
__device__ __forceinline__ float unpack_sum_(u64v2 v) {
    float lo, hi;
    asm("mov.b64 {%0, %1}, %2;" : "=f"(lo), "=f"(hi) : "l"(v));
    return lo + hi;
}
__device__ __forceinline__ u64v2 pack2_(float lo, float hi) {
    u64v2 r;
    asm("mov.b64 %0, {%1, %2};" : "=l"(r) : "f"(lo), "f"(hi));
    return r;
}

// ---------------- scratch ----------------
__device__ __align__(16) float g_G[(size_t)NTOK * GN];           // input proj + bias
__device__ __align__(16) float g_hseq[2 * SEQ * BSZ * HIDD];     // [dir][t][b][h]
__device__ __align__(16) float g_em[(size_t)NTOK * NTAG];        // emissions
__device__ float g_loss[BSZ];
__device__ unsigned g_cnt4[4 * 32];                              // flat barrier counters
__device__ unsigned g_gen4[4 * 32];                              // monotonic generations

// =====================================================================
// Kernel 1: G[token][n] = dot(emb[x[token]], W[n]) + bias[n]  (f32x2)
// =====================================================================
__global__ __launch_bounds__(256) void gemm_in(
    const int* __restrict__ x, const float* __restrict__ emb,
    const float* __restrict__ wf, const float* __restrict__ wb,
    const float* __restrict__ bf, const float* __restrict__ bb)
{
    __shared__ float sA[16 * 132];
    __shared__ float sW[16 * 132];
    const int tid = threadIdx.x;
    const int bx = blockIdx.x;
    const int by = blockIdx.y;
    const int tx = tid & 15, ty = tid >> 4;

    u64v2 acc2[8][4];
#pragma unroll
    for (int i = 0; i < 8; ++i)
#pragma unroll
        for (int j = 0; j < 4; ++j) acc2[i][j] = 0ull;

    const int f4a = tid * 2, f4b = tid * 2 + 1;
    const int ra = f4a >> 2, qa = (f4a & 3) * 4;
    const int rb = f4b >> 2, qb = (f4b & 3) * 4;
    const float* arow_a = emb + (size_t)x[by * 128 + ra] * EMBD;
    const float* arow_b = emb + (size_t)x[by * 128 + rb] * EMBD;
    const int na = bx * 128 + ra, nb = bx * 128 + rb;
    const float* wrow_a = (na < G4H) ? (wf + (size_t)na * EMBD) : (wb + (size_t)(na - G4H) * EMBD);
    const float* wrow_b = (nb < G4H) ? (wf + (size_t)nb * EMBD) : (wb + (size_t)(nb - G4H) * EMBD);

    for (int kb = 0; kb < EMBD; kb += 16) {
        __syncthreads();
        float4 va = *(const float4*)(arow_a + kb + qa);
        float4 vb = *(const float4*)(arow_b + kb + qb);
        float4 wa = *(const float4*)(wrow_a + kb + qa);
        float4 wv = *(const float4*)(wrow_b + kb + qb);
        sA[(qa + 0) * 132 + ra] = va.x; sA[(qa + 1) * 132 + ra] = va.y;
        sA[(qa + 2) * 132 + ra] = va.z; sA[(qa + 3) * 132 + ra] = va.w;
        sA[(qb + 0) * 132 + rb] = vb.x; sA[(qb + 1) * 132 + rb] = vb.y;
        sA[(qb + 2) * 132 + rb] = vb.z; sA[(qb + 3) * 132 + rb] = vb.w;
        sW[(qa + 0) * 132 + ra] = wa.x; sW[(qa + 1) * 132 + ra] = wa.y;
        sW[(qa + 2) * 132 + ra] = wa.z; sW[(qa + 3) * 132 + ra] = wa.w;
        sW[(qb + 0) * 132 + rb] = wv.x; sW[(qb + 1) * 132 + rb] = wv.y;
        sW[(qb + 2) * 132 + rb] = wv.z; sW[(qb + 3) * 132 + rb] = wv.w;
        __syncthreads();
#pragma unroll
        for (int kk = 0; kk < 16; ++kk) {
            float4 a0 = *(const float4*)&sA[kk * 132 + ty * 8];
            float4 a1 = *(const float4*)&sA[kk * 132 + ty * 8 + 4];
            ulonglong2 b0 = *(const ulonglong2*)&sW[kk * 132 + tx * 8];
            ulonglong2 b1 = *(const ulonglong2*)&sW[kk * 132 + tx * 8 + 4];
            float av[8] = {a0.x, a0.y, a0.z, a0.w, a1.x, a1.y, a1.z, a1.w};
#pragma unroll
            for (int i = 0; i < 8; ++i) {
                u64v2 aa = pack2_(av[i], av[i]);
                fma2_(acc2[i][0], aa, b0.x);
                fma2_(acc2[i][1], aa, b0.y);
                fma2_(acc2[i][2], aa, b1.x);
                fma2_(acc2[i][3], aa, b1.y);
            }
        }
    }
    const int m0 = by * 128 + ty * 8;
    const int n0 = bx * 128 + tx * 8;
#pragma unroll
    for (int i = 0; i < 8; ++i) {
        float* dst = g_G + (size_t)(m0 + i) * GN + n0;
#pragma unroll
        for (int p = 0; p < 4; ++p) {
            float lo, hi;
            asm("mov.b64 {%0, %1}, %2;" : "=f"(lo), "=f"(hi) : "l"(acc2[i][p]));
            int n_lo = n0 + 2 * p, n_hi = n_lo + 1;
            float bias_lo = (n_lo < G4H) ? bf[n_lo] : bb[n_lo - G4H];
            float bias_hi = (n_hi < G4H) ? bf[n_hi] : bb[n_hi - G4H];
            dst[2 * p]     = lo + bias_lo;
            dst[2 * p + 1] = hi + bias_hi;
        }
    }
}

// =====================================================================
// Kernel 2: persistent bidirectional LSTM — WARP-SPECIALIZED halves.
// Warps 0-3: batches 0-15; warps 4-7: batches 16-31. Each half is an
// independent lock-step stream (named barriers 1/2), so one half's
// inter-block barrier latency hides behind the other's compute.
// Arrival: flat 64-wide counter, atom.release.gpu by one thread;
// wait: ld.acquire.gpu poll. No membar.gl anywhere.
// =====================================================================
__device__ __forceinline__ float sigmoidf_(float v) { return 1.f / (1.f + __expf(-v)); }

__global__ __launch_bounds__(256) void lstm_rec(
    const float* __restrict__ whf, const float* __restrict__ whb)
{
    extern __shared__ float smemf[];
    float* sw = smemf;                                   // 32 rows x RS (shared by halves)

    const int tid = threadIdx.x;
    const int dir = blockIdx.x >> 6;
    const int blk = blockIdx.x & 63;
    const int jbase = blk * 8;
    const int half = tid >> 7;                           // batch group 0/1
    const int htid = tid & 127;
    const float* whh = dir ? whb : whf;

    float* sh  = smemf + (32 + half * 16) * RS;          // 16 rows x RS per half
    float* red = smemf + 64 * RS + half * (8 * 16 * 36); // [8 kseg][16 unit] x 36

    // cooperative w_hh load (all 256 threads), k-swizzled
    for (int idx = tid; idx < 32 * 128; idx += 256) {
        int row = idx >> 7;
        int q4 = idx & 127;
        int g = row >> 3, j = row & 7;
        float4 v = *(const float4*)(whh + (size_t)(g * 512 + jbase + j) * HIDD + q4 * 4);
        *(float4*)&sw[row * RS + q4 * 4 + 4 * (q4 >> 3)] = v;
    }

    // dot decomposition within half: 8 ksegs (64 k each) x 16 units
    const int kseg = htid >> 4;
    const int unit = htid & 15;
    const int jj = unit & 7;
    const int bo = unit >> 3;            // 0..1 (8 batches each)
    const int kb = kseg * 72;            // swizzled base of 64-k segment

    // finalize decomposition: thread owns (fj, fbl)
    const int fj = htid & 7;
    const int fbl = htid >> 3;           // 0..15
    const int fb = half * 16 + fbl;      // global batch
    const int jglob = jbase + fj;
    const int funit = fj + 8 * (fbl >> 3);
    const int fbb = fbl & 7;

    const int slot = (dir * 2 + half) * 32;
    unsigned gbase = 0;
    if (htid == 0) {
        asm volatile("ld.acquire.gpu.global.u32 %0, [%1];"
                     : "=r"(gbase) : "l"(&g_gen4[slot]) : "memory");
    }
    float c_state = 0.f;
    __syncthreads();                                     // w ready
    const int barid = 1 + half;

    for (int t = 0; t < SEQ; ++t) {
        const int t_eff = dir ? (SEQ - 1 - t) : t;
        const float* Grow = g_G + (size_t)(fb * SEQ + t_eff) * GN + dir * G4H;
        float pg0 = __ldg(Grow + jglob);
        float pg1 = __ldg(Grow + 512 + jglob);
        float pg2 = __ldg(Grow + 1024 + jglob);
        float pg3 = __ldg(Grow + 1536 + jglob);

        float d0 = 0.f, d1 = 0.f, d2 = 0.f, d3 = 0.f;
        if (t > 0) {
            if (htid == 0) {
                unsigned v;
                do {
                    asm volatile("ld.acquire.gpu.global.u32 %0, [%1];"
                                 : "=r"(v) : "l"(&g_gen4[slot]) : "memory");
                } while ((unsigned)(v - gbase) < (unsigned)t);
            }
            asm volatile("bar.sync %0, %1;" :: "r"(barid), "r"(128) : "memory");
            // stage this half's 16 h rows, k-swizzled
            const int prev_te = dir ? (t_eff + 1) : (t_eff - 1);
            const float* hsrc = g_hseq + (size_t)((dir * SEQ + prev_te) * BSZ + half * 16) * HIDD;
            for (int idx = htid; idx < 16 * 128; idx += 128) {
                int b = idx >> 7;
                int q4 = idx & 127;
                float4 v = __ldcg((const float4*)(hsrc + b * HIDD + q4 * 4));
                *(float4*)&sh[b * RS + q4 * 4 + 4 * (q4 >> 3)] = v;
            }
            asm volatile("bar.sync %0, %1;" :: "r"(barid), "r"(128) : "memory");
            // dot: 4 gate-rows x 8 batches x 64 k (two 32-k swizzle blocks)
            u64v2 acc2[4][8];
#pragma unroll
            for (int g = 0; g < 4; ++g)
#pragma unroll
                for (int bb = 0; bb < 8; ++bb) acc2[g][bb] = 0ull;
            const float* w0p = &sw[jj * RS + kb];
            const float* w1p = w0p + 8 * RS;
            const float* w2p = w0p + 16 * RS;
            const float* w3p = w0p + 24 * RS;
            const float* hp  = &sh[(bo * 8) * RS + kb];
#pragma unroll
            for (int sb = 0; sb < 2; ++sb) {
                const int so = sb * 36;
#pragma unroll
                for (int kk = 0; kk < 32; kk += 4) {
                    ulonglong2 w0 = *(const ulonglong2*)(w0p + so + kk);
                    ulonglong2 w1 = *(const ulonglong2*)(w1p + so + kk);
                    ulonglong2 w2 = *(const ulonglong2*)(w2p + so + kk);
                    ulonglong2 w3 = *(const ulonglong2*)(w3p + so + kk);
#pragma unroll
                    for (int bb = 0; bb < 8; ++bb) {
                        ulonglong2 h = *(const ulonglong2*)(hp + bb * RS + so + kk);
                        fma2_(acc2[0][bb], w0.x, h.x); fma2_(acc2[0][bb], w0.y, h.y);
                        fma2_(acc2[1][bb], w1.x, h.x); fma2_(acc2[1][bb], w1.y, h.y);
                        fma2_(acc2[2][bb], w2.x, h.x); fma2_(acc2[2][bb], w2.y, h.y);
                        fma2_(acc2[3][bb], w3.x, h.x); fma2_(acc2[3][bb], w3.y, h.y);
                    }
                }
            }
            float* rp = &red[(kseg * 16 + unit) * 36];
#pragma unroll
            for (int g = 0; g < 4; ++g) {
                float s0 = unpack_sum_(acc2[g][0]);
                float s1 = unpack_sum_(acc2[g][1]);
                float s2 = unpack_sum_(acc2[g][2]);
                float s3 = unpack_sum_(acc2[g][3]);
                float s4 = unpack_sum_(acc2[g][4]);
                float s5 = unpack_sum_(acc2[g][5]);
                float s6 = unpack_sum_(acc2[g][6]);
                float s7 = unpack_sum_(acc2[g][7]);
                *(float4*)&rp[g * 8]     = make_float4(s0, s1, s2, s3);
                *(float4*)&rp[g * 8 + 4] = make_float4(s4, s5, s6, s7);
            }
            asm volatile("bar.sync %0, %1;" :: "r"(barid), "r"(128) : "memory");
#pragma unroll
            for (int s = 0; s < 8; ++s) {
                const float* rr = &red[(s * 16 + funit) * 36];
                d0 += rr[fbb];
                d1 += rr[8 + fbb];
                d2 += rr[16 + fbb];
                d3 += rr[24 + fbb];
            }
        }
        // gates + state update
        {
            float gi = pg0 + d0;
            float gf = pg1 + d1;
            float gg = pg2 + d2;
            float go = pg3 + d3;
            float iv = sigmoidf_(gi);
            float fv = sigmoidf_(gf);
            float ov = sigmoidf_(go);
            float gv = tanhf(gg);
            c_state = fv * c_state + iv * gv;
            float hv = ov * tanhf(c_state);
            __stcg(&g_hseq[(size_t)((dir * SEQ + t_eff) * BSZ + fb) * HIDD + jglob], hv);
        }
        asm volatile("bar.sync %0, %1;" :: "r"(barid), "r"(128) : "memory");
        if (htid == 0) {
            unsigned old;
            asm volatile("atom.release.gpu.global.add.u32 %0, [%1], %2;"
                         : "=r"(old) : "l"(&g_cnt4[slot]), "r"(1u) : "memory");
            if (old == 63u) {
                asm volatile("st.global.u32 [%0], %1;"
                             :: "l"(&g_cnt4[slot]), "r"(0u) : "memory");
                unsigned ng = gbase + (unsigned)t + 1u;
                asm volatile("st.release.gpu.global.u32 [%0], %1;"
                             :: "l"(&g_gen4[slot]), "r"(ng) : "memory");
            }
        }
    }
}

// =====================================================================
// Kernel 3: emissions
// =====================================================================
__device__ __forceinline__ float dot4_(float4 a, float4 b) {
    return a.x * b.x + a.y * b.y + a.z * b.z + a.w * b.w;
}

__global__ __launch_bounds__(256) void emis_k(
    const float* __restrict__ lw, const float* __restrict__ lb)
{
    __shared__ float shh[32 * 132];
    __shared__ float shw[48 * 132];
    const int tid = threadIdx.x;
    const int blk = blockIdx.x;
    const int b = blk >> 3;
    const int s0 = (blk & 7) * 32;
    const int tt = tid & 15;
    const int tg = tid >> 4;
    float acc[2][3] = {{0.f, 0.f, 0.f}, {0.f, 0.f, 0.f}};

    for (int kc = 0; kc < 1024; kc += 128) {
        __syncthreads();
        const int dk = kc >> 9;
        const int ko = kc & 511;
        for (int idx = tid; idx < 32 * 32; idx += 256) {
            int ti = idx >> 5;
            int q = (idx & 31) * 4;
            *(float4*)&shh[ti * 132 + q] =
                *(const float4*)&g_hseq[(size_t)((dk * SEQ + (s0 + ti)) * BSZ + b) * HIDD + ko + q];
        }
        for (int idx = tid; idx < 48 * 32; idx += 256) {
            int tag = idx >> 5;
            int q = (idx & 31) * 4;
            float4 v = make_float4(0.f, 0.f, 0.f, 0.f);
            if (tag < NTAG) v = *(const float4*)&lw[(size_t)tag * 1024 + kc + q];
            *(float4*)&shw[tag * 132 + q] = v;
        }
        __syncthreads();
#pragma unroll 8
        for (int kk = 0; kk < 128; kk += 4) {
            float4 h0 = *(const float4*)&shh[tt * 132 + kk];
            float4 h1 = *(const float4*)&shh[(tt + 16) * 132 + kk];
            float4 w0 = *(const float4*)&shw[tg * 132 + kk];
            float4 w1 = *(const float4*)&shw[(tg + 16) * 132 + kk];
            float4 w2 = *(const float4*)&shw[(tg + 32) * 132 + kk];
            acc[0][0] += dot4_(h0, w0); acc[0][1] += dot4_(h0, w1); acc[0][2] += dot4_(h0, w2);
            acc[1][0] += dot4_(h1, w0); acc[1][1] += dot4_(h1, w1); acc[1][2] += dot4_(h1, w2);
        }
    }
#pragma unroll
    for (int ti = 0; ti < 2; ++ti) {
        int token = b * SEQ + s0 + tt + ti * 16;
#pragma unroll
        for (int c = 0; c < 3; ++c) {
            int tag = tg + c * 16;
            if (tag < NTAG)
                g_em[(size_t)token * NTAG + tag] = acc[ti][c] + lb[tag];
        }
    }
}

// =====================================================================
// Kernel 4: CRF — one WARP per batch (proven), exp-domain forward with
// lazy renorm (every 8 steps). 4 warps/block, grid 8.
// =====================================================================
__global__ __launch_bounds__(128) void crf_k(
    const int* __restrict__ tags, const float* __restrict__ st,
    const float* __restrict__ et, const float* __restrict__ tr)
{
    __shared__ float str[NTAG * NTAG];
    __shared__ float sE[NTAG * 48];
    __shared__ float sa[4][2][48];
    const int tid = threadIdx.x;
    const int wid = tid >> 5;
    const int lane = tid & 31;
    const int b = blockIdx.x * 4 + wid;
    const int* tg = tags + b * SEQ;

    for (int i = tid; i < NTAG * NTAG; i += 128) str[i] = tr[i];
    __syncthreads();
    for (int idx = tid; idx < NTAG * NTAG; idx += 128) {
        int i = idx / NTAG, col = idx % NTAG;
        sE[i * 48 + col] = __expf(str[idx]);
    }
    __syncthreads();

    float part = 0.f;
    for (int s = lane; s < SEQ; s += 32) {
        int cur = tg[s];
        part += g_em[(size_t)(b * SEQ + s) * NTAG + cur];
        if (s + 1 < SEQ) part += str[cur * NTAG + tg[s + 1]];
    }
#pragma unroll
    for (int off = 16; off; off >>= 1)
        part += __shfl_xor_sync(0xffffffffu, part, off);

    const int c0 = lane;
    const bool has1 = (lane < 13);
    const int c1 = has1 ? lane + 32 : lane;
    float* a0 = sa[wid][0];
    float* a1 = sa[wid][1];

    float i0 = st[c0] + g_em[(size_t)(b * SEQ) * NTAG + c0];
    float i1 = has1 ? (st[c1] + g_em[(size_t)(b * SEQ) * NTAG + c1]) : -1e30f;
    float m = fmaxf(i0, i1);
#pragma unroll
    for (int off = 16; off; off >>= 1)
        m = fmaxf(m, __shfl_xor_sync(0xffffffffu, m, off));
    float logacc = m;
    a0[c0] = __expf(i0 - m);
    if (has1) a0[c1] = __expf(i1 - m);
    __syncwarp();

    float e0 = g_em[(size_t)(b * SEQ + 1) * NTAG + c0];
    float e1 = has1 ? g_em[(size_t)(b * SEQ + 1) * NTAG + c1] : 0.f;
    int cur = 0;
    for (int t = 1; t < SEQ; ++t) {
        float n0 = 0.f, n1 = 0.f;
        if (t + 1 < SEQ) {
            n0 = g_em[(size_t)(b * SEQ + t + 1) * NTAG + c0];
            if (has1) n1 = g_em[(size_t)(b * SEQ + t + 1) * NTAG + c1];
        }
        const float* a = cur ? a1 : a0;
        float* an = cur ? a0 : a1;
        float s0 = 0.f, s1 = 0.f;
#pragma unroll 9
        for (int i = 0; i < NTAG; ++i) {
            float ai = a[i];
            s0 += sE[i * 48 + c0] * ai;
            s1 += sE[i * 48 + c1] * ai;
        }
        float v0 = s0 * __expf(e0);
        an[c0] = v0;
        float v1 = 0.f;
        if (has1) { v1 = s1 * __expf(e1); an[c1] = v1; }
        __syncwarp();
        cur ^= 1;
        if ((t & 7) == 0) {
            float mm = fmaxf(v0, v1);
#pragma unroll
            for (int off = 16; off; off >>= 1)
                mm = fmaxf(mm, __shfl_xor_sync(0xffffffffu, mm, off));
            float inv = 1.f / mm;
            float* ac = cur ? a1 : a0;
            ac[c0] *= inv;
            if (has1) ac[c1] *= inv;
            logacc += __logf(mm);
            __syncwarp();
        }
        e0 = n0; e1 = n1;
    }

    const float* af = cur ? a1 : a0;
    float ssum = af[c0] * __expf(et[c0]);
    if (has1) ssum += af[c1] * __expf(et[c1]);
#pragma unroll
    for (int off = 16; off; off >>= 1)
        ssum += __shfl_xor_sync(0xffffffffu, ssum, off);

    if (lane == 0) {
        float sc = part + st[tg[0]] + et[tg[SEQ - 1]];
        float logZ = logacc + __logf(ssum);
        g_loss[b] = logZ - sc;
    }
}

__global__ void final_reduce(float* __restrict__ out)
{
    if (threadIdx.x == 0) {
        float s = 0.f;
        for (int i = 0; i < BSZ; ++i) s += g_loss[i];
        out[0] = s / (float)BSZ;
    }
}

// =====================================================================
extern "C" void kernel_launch(void* const* d_in, const int* in_sizes, int n_in,
                              void* d_out, int out_size)
{
    (void)in_sizes; (void)n_in; (void)out_size;
    const int*   x   = (const int*)d_in[0];
    const int*   tgs = (const int*)d_in[1];
    const float* emb = (const float*)d_in[2];
    const float* wif = (const float*)d_in[3];
    const float* whf = (const float*)d_in[4];
    const float* bf  = (const float*)d_in[5];
    const float* wib = (const float*)d_in[6];
    const float* whb = (const float*)d_in[7];
    const float* bb  = (const float*)d_in[8];
    const float* lw  = (const float*)d_in[9];
    const float* lb  = (const float*)d_in[10];
    const float* st  = (const float*)d_in[11];
    const float* et  = (const float*)d_in[12];
    const float* tr  = (const float*)d_in[13];
    float* out = (float*)d_out;

    const int rec_smem = (64 * RS + 2 * 8 * 16 * 36) * 4;   // 183296 B
    cudaFuncSetAttribute(lstm_rec, cudaFuncAttributeMaxDynamicSharedMemorySize, rec_smem);

    dim3 gemm_grid(32, 64);
    gemm_in<<<gemm_grid, 256>>>(x, emb, wif, wib, bf, bb);
    lstm_rec<<<128, 256, rec_smem>>>(whf, whb);
    emis_k<<<256, 256>>>(lw, lb);
    crf_k<<<8, 128>>>(tgs, st, et, tr);
    final_reduce<<<1, 32>>>(out);
}